// round 13
// baseline (speedup 1.0000x reference)
#include <cuda_runtime.h>
#include <cuda_bf16.h>
#include <math.h>
#include <stdint.h>

#define Bb   4
#define Dd   64
#define Hh   4
#define DHd  16
#define Nn   2304
#define BHh  16   // B*heads

#define LOG2E 1.4426950408889634f
#define SC    0.8493218593f   // sqrt(0.5*log2e)

// ---------------- scratch (device globals) ----------------------------------
__device__ uint32_t d_qb[BHh * Nn * 8];          // q bf16x2: [bh][n][k/2], scaled by SC
__device__ float d_qn[BHh * Nn];                 // 0.25*log2e*||q||^2
__device__ __nv_bfloat16 d_zb[BHh * DHd * Nn];   // Z bf16: [bh][c][m]
__device__ float d_us[2][BHh * Nn * DHd];        // partial O (unnormalized), permuted rows
__device__ float d_ls[2][BHh * Nn];              // partial li, permuted rows
__device__ float d_cat[Bb * Dd * Nn];            // cat_img[b][dd][n]
__device__ float d_bound[1];

__device__ __forceinline__ float ex2(float a) {
    float r;
    asm("ex2.approx.ftz.f32 %0, %1;" : "=f"(r) : "f"(a));
    return r;
}
__device__ __forceinline__ uint32_t cvt2(float lo, float hi) {
    uint32_t r;
    asm("cvt.rn.bf16x2.f32 %0, %1, %2;" : "=r"(r) : "f"(hi), "f"(lo));
    return r;
}
__device__ __forceinline__ uint32_t smem_u32(const void* p) {
    return (uint32_t)__cvta_generic_to_shared(p);
}
__device__ __forceinline__ void ldsm4(uint32_t& r0, uint32_t& r1, uint32_t& r2, uint32_t& r3,
                                      uint32_t addr) {
    asm volatile("ldmatrix.sync.aligned.m8n8.x4.shared.b16 {%0,%1,%2,%3}, [%4];"
                 : "=r"(r0), "=r"(r1), "=r"(r2), "=r"(r3) : "r"(addr));
}
__device__ __forceinline__ void mma16816(float& d0, float& d1, float& d2, float& d3,
                                         uint32_t a0, uint32_t a1, uint32_t a2, uint32_t a3,
                                         uint32_t b0, uint32_t b1,
                                         float c0, float c1, float c2, float c3) {
    asm volatile("mma.sync.aligned.m16n8k16.row.col.f32.bf16.bf16.f32 "
                 "{%0,%1,%2,%3},{%4,%5,%6,%7},{%8,%9},{%10,%11,%12,%13};"
                 : "=f"(d0), "=f"(d1), "=f"(d2), "=f"(d3)
                 : "r"(a0), "r"(a1), "r"(a2), "r"(a3), "r"(b0), "r"(b1),
                   "f"(c0), "f"(c1), "f"(c2), "f"(c3));
}

// ---------------- K_qz: z==0 -> q all heads; z==1 -> Z all heads; z==2 -> bound
__global__ void __launch_bounds__(128) k_qz(const float* __restrict__ x,
                                            const float* __restrict__ Wq,
                                            const float* __restrict__ bq,
                                            const float* __restrict__ Wv,
                                            const float* __restrict__ Wo) {
    __shared__ float sW[Hh * DHd * Dd];   // 4096 floats: all heads
    int tid = threadIdx.x;
    int z = blockIdx.z;
    int b = blockIdx.y;

    if (z == 2) {
        if (blockIdx.x != 0 || blockIdx.y != 0) return;
        __shared__ float red[128];
        __shared__ float sq[Hh], sv[Hh];
        for (int h = 0; h < Hh; h++) {
            float a = 0.f;
            for (int i = tid; i < 1024; i += 128) { float w = Wq[h * 1024 + i]; a += w * w; }
            red[tid] = a; __syncthreads();
            for (int s = 64; s > 0; s >>= 1) { if (tid < s) red[tid] += red[tid + s]; __syncthreads(); }
            if (tid == 0) sq[h] = red[0];
            __syncthreads();
            a = 0.f;
            for (int i = tid; i < 1024; i += 128) { float w = Wv[h * 1024 + i]; a += w * w; }
            red[tid] = a; __syncthreads();
            for (int s = 64; s > 0; s >>= 1) { if (tid < s) red[tid] += red[tid + s]; __syncthreads(); }
            if (tid == 0) sv[h] = red[0];
            __syncthreads();
        }
        float a = 0.f;
        for (int i = tid; i < 4096; i += 128) { float w = Wo[i]; a += w * w; }
        red[tid] = a; __syncthreads();
        for (int s = 64; s > 0; s >>= 1) { if (tid < s) red[tid] += red[tid + s]; __syncthreads(); }
        if (tid == 0) {
            double zz = 2304.0 / 2.718281828459045;
            double w = log(zz) - log(log(zz));
            for (int it = 0; it < 30; it++) {
                double ew = exp(w);
                w = w - (w * ew - zz) / (ew * (w + 1.0));
            }
            float phi = (float)w;
            float term = sqrtf(sq[0] * sv[0] + sq[1] * sv[1] + sq[2] * sv[2] + sq[3] * sv[3]);
            d_bound[0] = sqrtf(2304.f / 64.f) * (4.f * phi + 1.f) * term * sqrtf(red[0]);
        }
        return;
    }

    for (int i = tid; i < 4096; i += 128) sW[i] = Wq[i];
    __syncthreads();

    if (z == 0) {
        int n = blockIdx.x * 128 + tid;
        const float* xb = x + b * Dd * Nn;
        float xv[Dd];
#pragma unroll
        for (int d = 0; d < Dd; d++) xv[d] = xb[d * Nn + n];
        for (int h = 0; h < Hh; h++) {
            int bh = b * Hh + h;
            float qv[DHd];
            float qn = 0.f;
#pragma unroll
            for (int k = 0; k < DHd; k++) {
                float acc = bq[h * DHd + k];
                const float* w = sW + (h * DHd + k) * Dd;
#pragma unroll
                for (int d = 0; d < Dd; d++) acc += w[d] * xv[d];
                qv[k] = acc;
                qn += acc * acc;
            }
            uint32_t pk[8];
#pragma unroll
            for (int i = 0; i < 8; i++) pk[i] = cvt2(SC * qv[2 * i], SC * qv[2 * i + 1]);
            uint4* dst = (uint4*)(d_qb + ((size_t)bh * Nn + n) * 8);
            dst[0] = make_uint4(pk[0], pk[1], pk[2], pk[3]);
            dst[1] = make_uint4(pk[4], pk[5], pk[6], pk[7]);
            d_qn[(size_t)bh * Nn + n] = qn * (0.25f * LOG2E);
        }
    } else {
        int m = blockIdx.x * 128 + tid;
        const float* xr = x + (size_t)b * Dd * Nn + (size_t)m * Dd;
        float xv[Dd];
#pragma unroll
        for (int dc = 0; dc < 16; dc++) {
            float4 v = *(const float4*)(xr + dc * 4);
            xv[dc * 4 + 0] = v.x; xv[dc * 4 + 1] = v.y;
            xv[dc * 4 + 2] = v.z; xv[dc * 4 + 3] = v.w;
        }
        for (int h = 0; h < Hh; h++) {
            int bh = b * Hh + h;
            float acc[DHd];
#pragma unroll
            for (int c = 0; c < DHd; c++) acc[c] = 0.f;
#pragma unroll
            for (int d = 0; d < Dd; d++) {
                float xd = xv[d];
                const float4* rr = (const float4*)(sW + h * 1024 + d * 16);
#pragma unroll
                for (int cc = 0; cc < 4; cc++) {
                    float4 rv = rr[cc];
                    acc[cc * 4 + 0] += xd * rv.x;
                    acc[cc * 4 + 1] += xd * rv.y;
                    acc[cc * 4 + 2] += xd * rv.z;
                    acc[cc * 4 + 3] += xd * rv.w;
                }
            }
#pragma unroll
            for (int c = 0; c < DHd; c++)
                d_zb[((size_t)bh * DHd + c) * Nn + m] = __float2bfloat16_rn(acc[c]);
        }
    }
}

// ---------------- K1: flash, split-m (z halves), unnormalized partials ------
__global__ void __launch_bounds__(256) k_flash() {
    int bh = blockIdx.y;
    int zid = blockIdx.z;               // m-half: tiles [zid*18, zid*18+18)
    int n0 = blockIdx.x * 128;
    int tid = threadIdx.x;
    int w = tid >> 5, lane = tid & 31;
    int grp = lane >> 3, lr = lane & 7;

    __shared__ __align__(16) __nv_bfloat16 sQ[128 * 24];     // rows n, pitch 24
    __shared__ __align__(16) __nv_bfloat16 sK[2][64 * 24];   // rows m, pitch 24
    __shared__ __align__(16) __nv_bfloat16 sZ[2][16 * 72];   // rows c, pitch 72
    __shared__ float sKn[2][64];

    const uint4* qb4 = (const uint4*)d_qb + (size_t)bh * Nn * 2;
    const __nv_bfloat16* zb = d_zb + (size_t)bh * DHd * Nn;
    const float* qnb = d_qn + (size_t)bh * Nn;

    int mbase = zid * 1152;             // 18 tiles * 64

    int krow = tid >> 1, khalf = tid & 1;
    int zc = (tid - 128) >> 3, zseg = (tid - 128) & 7;

    {
        int row = tid >> 1, half = tid & 1;
        *(uint4*)(sQ + row * 24 + half * 8) = qb4[(size_t)(n0 + row) * 2 + half];
    }
    if (tid < 128) *(uint4*)(sK[0] + krow * 24 + khalf * 8) = qb4[(size_t)(mbase + krow) * 2 + khalf];
    else           *(uint4*)(sZ[0] + zc * 72 + zseg * 8) = *(const uint4*)(zb + (size_t)zc * Nn + mbase + zseg * 8);
    if (tid < 64)  sKn[0][tid] = qnb[mbase + tid];
    __syncthreads();

    uint32_t qa0, qa1, qa2, qa3;
    {
        uint32_t addr = smem_u32(sQ) + ((w * 16 + (grp & 1) * 8 + lr) * 24 + (grp >> 1) * 8) * 2;
        ldsm4(qa0, qa1, qa2, qa3, addr);
    }
    float nq0 = -qnb[n0 + w * 16 + (lane >> 2)];
    float nq1 = -qnb[n0 + w * 16 + (lane >> 2) + 8];

    uint32_t AKb0 = smem_u32(sK[0]) + (((grp >> 1) * 8 + lr) * 24 + (grp & 1) * 8) * 2;
    uint32_t AZb0 = smem_u32(sZ[0]) + ((grp >> 1) * 8 + lr) * 144 + ((grp & 1) * 8) * 2;
    const uint32_t KBUF = 64 * 24 * 2, ZBUF = 16 * 72 * 2;

    float O[2][4];
#pragma unroll
    for (int u = 0; u < 2; u++)
#pragma unroll
        for (int k = 0; k < 4; k++) O[u][k] = 0.f;
    float li0 = 0.f, li1 = 0.f;

    for (int t = 0; t < 18; t++) {
        int cur = t & 1;
        uint4 pK, pZ;
        float pN;
        if (t < 17) {
            int m0 = mbase + (t + 1) * 64;
            if (tid < 128) pK = qb4[(size_t)(m0 + krow) * 2 + khalf];
            else           pZ = *(const uint4*)(zb + (size_t)zc * Nn + m0 + zseg * 8);
            if (tid < 64)  pN = qnb[m0 + tid];
        }

        uint32_t kf[8][2];
#pragma unroll
        for (int s = 0; s < 4; s++) {
            uint32_t r0, r1, r2, r3;
            ldsm4(r0, r1, r2, r3, AKb0 + cur * KBUF + s * 768);
            kf[2 * s][0] = r0; kf[2 * s][1] = r1;
            kf[2 * s + 1][0] = r2; kf[2 * s + 1][1] = r3;
        }

        float p[8][4];
#pragma unroll
        for (int j = 0; j < 8; j++) {
            float2 kn2 = *(const float2*)&sKn[cur][8 * j + 2 * (lane & 3)];
            float d0, d1, d2, d3;
            mma16816(d0, d1, d2, d3, qa0, qa1, qa2, qa3, kf[j][0], kf[j][1],
                     nq0 - kn2.x, nq0 - kn2.y, nq1 - kn2.x, nq1 - kn2.y);
            p[j][0] = ex2(d0); p[j][1] = ex2(d1);
            p[j][2] = ex2(d2); p[j][3] = ex2(d3);
            li0 += p[j][0] + p[j][1];
            li1 += p[j][2] + p[j][3];
        }

#pragma unroll
        for (int s = 0; s < 4; s++) {
            uint32_t z0, z1, z2, z3;
            ldsm4(z0, z1, z2, z3, AZb0 + cur * ZBUF + s * 32);
            uint32_t a0 = cvt2(p[2 * s][0], p[2 * s][1]);
            uint32_t a1 = cvt2(p[2 * s][2], p[2 * s][3]);
            uint32_t a2 = cvt2(p[2 * s + 1][0], p[2 * s + 1][1]);
            uint32_t a3 = cvt2(p[2 * s + 1][2], p[2 * s + 1][3]);
            mma16816(O[0][0], O[0][1], O[0][2], O[0][3], a0, a1, a2, a3, z0, z1,
                     O[0][0], O[0][1], O[0][2], O[0][3]);
            mma16816(O[1][0], O[1][1], O[1][2], O[1][3], a0, a1, a2, a3, z2, z3,
                     O[1][0], O[1][1], O[1][2], O[1][3]);
        }

        if (t < 17) {
            int nxt = 1 - cur;
            if (tid < 128) *(uint4*)(sK[nxt] + krow * 24 + khalf * 8) = pK;
            else           *(uint4*)(sZ[nxt] + zc * 72 + zseg * 8) = pZ;
            if (tid < 64)  sKn[nxt][tid] = pN;
        }
        __syncthreads();
    }

    li0 += __shfl_xor_sync(0xffffffffu, li0, 1);
    li0 += __shfl_xor_sync(0xffffffffu, li0, 2);
    li1 += __shfl_xor_sync(0xffffffffu, li1, 1);
    li1 += __shfl_xor_sync(0xffffffffu, li1, 2);

    int r0 = n0 + w * 16 + (lane >> 2);
    int r1 = r0 + 8;
    int pr0 = (r0 % 36) * 64 + r0 / 36;
    int pr1 = (r1 % 36) * 64 + r1 / 36;
    int cb = 2 * (lane & 3);
    float* ub = d_us[zid] + (size_t)bh * Nn * 16;
    float* lb = d_ls[zid] + (size_t)bh * Nn;
    float* ur0 = ub + (size_t)pr0 * 16;
    float* ur1 = ub + (size_t)pr1 * 16;
    *(float2*)(ur0 + cb)     = make_float2(O[0][0], O[0][1]);
    *(float2*)(ur0 + cb + 8) = make_float2(O[1][0], O[1][1]);
    *(float2*)(ur1 + cb)     = make_float2(O[0][2], O[0][3]);
    *(float2*)(ur1 + cb + 8) = make_float2(O[1][2], O[1][3]);
    if ((lane & 3) == 0) {
        lb[pr0] = li0;
        lb[pr1] = li1;
    }
}

// ---------------- K_gv: combine partials, fused g/v -> cat layout ------------
__global__ void __launch_bounds__(256) k_gv(const float* __restrict__ Wq,
                                            const float* __restrict__ Wv,
                                            const float* __restrict__ bv) {
    int bh = blockIdx.y;
    int h = bh & 3;
    int b = bh >> 2;
    int a = blockIdx.x;
    int tid = threadIdx.x;

    __shared__ float sT[64][17];   // T[dd][c] = U[a*64+dd][c]
    __shared__ float sWv[1024];
    __shared__ float sR[64][17];
    __shared__ float sM[16][17];

    {
        int dd = tid >> 2, cg = tid & 3;
        size_t row = (size_t)bh * Nn + a * 64 + dd;
        float4 v0 = *(const float4*)(d_us[0] + row * 16 + cg * 4);
        float4 v1 = *(const float4*)(d_us[1] + row * 16 + cg * 4);
        float inv = 1.f / (d_ls[0][row] + d_ls[1][row]);
        sT[dd][cg * 4 + 0] = (v0.x + v1.x) * inv;
        sT[dd][cg * 4 + 1] = (v0.y + v1.y) * inv;
        sT[dd][cg * 4 + 2] = (v0.z + v1.z) * inv;
        sT[dd][cg * 4 + 3] = (v0.w + v1.w) * inv;
        float4 rv = *(const float4*)(Wq + h * 1024 + dd * 16 + cg * 4);
        sR[dd][cg * 4 + 0] = rv.x; sR[dd][cg * 4 + 1] = rv.y;
        sR[dd][cg * 4 + 2] = rv.z; sR[dd][cg * 4 + 3] = rv.w;
    }
    for (int i = tid; i < 1024; i += 256) sWv[i] = Wv[h * 1024 + i];
    __syncthreads();

    {
        int k = tid >> 4, c = tid & 15;
        float acc = 0.f;
#pragma unroll
        for (int dd = 0; dd < 64; dd++) acc += sWv[k * 64 + dd] * sT[dd][c];
        sM[k][c] = acc;
    }
    __syncthreads();

    {
        int r = tid & 63, kg = tid >> 6;
        float vacc[4] = {0.f, 0.f, 0.f, 0.f};
#pragma unroll
        for (int c = 0; c < 16; c++) {
            float rc = sR[r][c];
            vacc[0] += sM[kg * 4 + 0][c] * rc;
            vacc[1] += sM[kg * 4 + 1][c] * rc;
            vacc[2] += sM[kg * 4 + 2][c] * rc;
            vacc[3] += sM[kg * 4 + 3][c] * rc;
        }
        int rq = r >> 4, kkl = r & 15;
#pragma unroll
        for (int kk2 = 0; kk2 < 4; kk2++) {
            int k = kg * 4 + kk2;
            float val = bv[h * 16 + k] + 0.25f * vacc[kk2];
            int s = k * 144 + a * 4 + rq;
            int dd_c = s / 36;
            int a_c = s - dd_c * 36;
            int n_c = a_c * 64 + h * 16 + kkl;
            d_cat[((size_t)(b * 64 + dd_c)) * Nn + n_c] = val;
        }
    }
}

// ---------------- K_out: 64(n) x 16(o) tiles, 576 blocks, float4 loads ------
__global__ void __launch_bounds__(256) k_out(const float* __restrict__ Wo,
                                             const float* __restrict__ bo,
                                             const float* __restrict__ gamma,
                                             const float* __restrict__ x,
                                             float* __restrict__ out) {
    int b = blockIdx.y;
    int n0 = blockIdx.x * 64;
    int ob = blockIdx.z * 16;
    int tid = threadIdx.x, ty = tid >> 4, tx = tid & 15;
    __shared__ __align__(16) float sC[64][68];
    __shared__ __align__(16) float sW[16][64];
    for (int i = tid; i < 1024; i += 256) {
        int dd = i >> 4, jj = (i & 15) * 4;
        *(float4*)(&sC[dd][jj]) = *(const float4*)(d_cat + ((size_t)(b * 64 + dd)) * Nn + n0 + jj);
    }
    {
        int row = tid >> 4, col = (tid & 15) * 4;
        *(float4*)(&sW[row][col]) = *(const float4*)(Wo + (ob + row) * 64 + col);
    }
    __syncthreads();
    float a0 = 0.f, a1 = 0.f, a2 = 0.f, a3 = 0.f;
#pragma unroll 16
    for (int dd = 0; dd < 64; dd++) {
        float wv = sW[ty][dd];
        float4 cv = *(const float4*)(&sC[dd][tx * 4]);
        a0 += wv * cv.x;
        a1 += wv * cv.y;
        a2 += wv * cv.z;
        a3 += wv * cv.w;
    }
    float scale = gamma[0] / d_bound[0];
    int o = ob + ty;
    float bb = bo[o];
    size_t base = ((size_t)b * 64 + o) * Nn + n0 + tx * 4;
    float4 xin = *(const float4*)(&x[base]);
    float4 r;
    r.x = scale * (a0 + bb) + xin.x;
    r.y = scale * (a1 + bb) + xin.y;
    r.z = scale * (a2 + bb) + xin.z;
    r.w = scale * (a3 + bb) + xin.w;
    *(float4*)(&out[base]) = r;
}

// ---------------- launch -----------------------------------------------------
extern "C" void kernel_launch(void* const* d_in, const int* in_sizes, int n_in,
                              void* d_out, int out_size) {
    const float* x     = (const float*)d_in[0];
    const float* Wq    = (const float*)d_in[1];
    const float* bq    = (const float*)d_in[2];
    const float* Wv    = (const float*)d_in[3];
    const float* bv    = (const float*)d_in[4];
    const float* Wo    = (const float*)d_in[5];
    const float* bo    = (const float*)d_in[6];
    const float* gamma = (const float*)d_in[7];
    float* out = (float*)d_out;

    k_qz   <<<dim3(Nn / 128, Bb, 3), 128>>>(x, Wq, bq, Wv, Wo);
    k_flash<<<dim3(Nn / 128, BHh, 2), 256>>>();
    k_gv   <<<dim3(36, BHh), 256>>>(Wq, Wv, bv);
    k_out  <<<dim3(Nn / 64, Bb, 4), 256>>>(Wo, bo, gamma, x, out);
}